// round 1
// baseline (speedup 1.0000x reference)
#include <cuda_runtime.h>
#include <math.h>

// FeedForwardQuantum: out = cos(relu(x@W1 + b1) + theta) @ W2 + b2
// x:[N=32768,1024] W1:[1024,16] b1:[16] theta:[16] W2:[16,1024] b2:[1024]
//
// Design:
//  - 256 threads/CTA, 256 rows/CTA, grid = N/256 = 128.
//  - GEMM1: one row per lane. W1 pre-interleaved in smem as d-pairs so every
//    FFMA2 (fma.rn.f32x2) operand comes straight from a broadcast LDS.128.
//    x staged gmem->smem in 32-d chunks (conflict-free stride-36 layout) with
//    register prefetch of the next chunk overlapping compute.
//  - z = cos(relu(h+b1)+theta) stored duplicated ((z,z) pairs) in smem.
//  - GEMM2: W2 held in registers (16q x 4d per thread), z via broadcast
//    LDS.128, coalesced STG.128 output.

#define DDIM 1024
#define QDIM 16
#define ROWS 256
#define NTHREADS 256
#define DCHUNK 32
#define NCHUNK (DDIM / DCHUNK)
#define XS_STRIDE 36
#define ZS_STRIDE 36

typedef unsigned long long u64;

__device__ __forceinline__ void ffma2(u64 &d, u64 a, u64 b) {
    asm("fma.rn.f32x2 %0, %1, %2, %0;" : "+l"(d) : "l"(a), "l"(b));
}
__device__ __forceinline__ float2 unpk(u64 v) {
    float2 f;
    asm("mov.b64 {%0,%1}, %2;" : "=f"(f.x), "=f"(f.y) : "l"(v));
    return f;
}
__device__ __forceinline__ u64 pk(float x, float y) {
    u64 v;
    asm("mov.b64 %0, {%1,%2};" : "=l"(v) : "f"(x), "f"(y));
    return v;
}

__global__ void __launch_bounds__(NTHREADS, 1)
ffq_kernel(const float* __restrict__ x, const float* __restrict__ W1,
           const float* __restrict__ b1, const float* __restrict__ theta,
           const float* __restrict__ W2, const float* __restrict__ b2,
           float* __restrict__ out, int nRows)
{
    extern __shared__ float sm[];
    float* w1p = sm;                        // 16384 floats (pair-interleaved W1)
    float* xs  = w1p + DDIM * QDIM;         // 256*36 floats
    float* zs  = xs + ROWS * XS_STRIDE;     // 256*36 floats (duplicated z)
    float* b1s = zs + ROWS * ZS_STRIDE;     // 16
    float* ths = b1s + QDIM;                // 16

    const int tid  = threadIdx.x;
    const int row0 = blockIdx.x * ROWS;

    // ---- stage W1 into pair-interleaved layout ----
    // w1p[b*32 + 2q + p] = W1[(2b+p)*16 + q]  (b = d/2, p in {0,1})
    for (int o = tid; o < DDIM * QDIM; o += NTHREADS) {
        int b = o >> 5;
        int r = o & 31;
        int q = r >> 1;
        int p = r & 1;
        w1p[o] = W1[(2 * b + p) * QDIM + q];
    }
    if (tid < QDIM) { b1s[tid] = b1[tid]; ths[tid] = theta[tid]; }

    // ---- GEMM1: row-per-lane, f32x2 accumulators over d-pairs ----
    u64 acc[QDIM];
#pragma unroll
    for (int q = 0; q < QDIM; q++) acc[q] = 0ULL;

    // staging mapping: per chunk, thread owns 8 float4s:
    //   element i = tid + 256k -> local row (tid>>3)+32k, col4 (tid&7)*4
    const int c4 = (tid & 7) * 4;
    const int rb = tid >> 3;

    float4 pf[8];
    // prefetch chunk 0
#pragma unroll
    for (int k = 0; k < 8; k++) {
        int gr = row0 + rb + 32 * k;
        if (gr >= nRows) gr = nRows - 1;
        pf[k] = *reinterpret_cast<const float4*>(x + (size_t)gr * DDIM + 0 + c4);
    }

    for (int ch = 0; ch < NCHUNK; ch++) {
        // store prefetched chunk to smem (conflict-free STS.128)
#pragma unroll
        for (int k = 0; k < 8; k++) {
            *reinterpret_cast<float4*>(xs + (rb + 32 * k) * XS_STRIDE + c4) = pf[k];
        }
        __syncthreads();

        // prefetch next chunk while computing this one
        if (ch + 1 < NCHUNK) {
            int dbn = (ch + 1) * DCHUNK;
#pragma unroll
            for (int k = 0; k < 8; k++) {
                int gr = row0 + rb + 32 * k;
                if (gr >= nRows) gr = nRows - 1;
                pf[k] = *reinterpret_cast<const float4*>(x + (size_t)gr * DDIM + dbn + c4);
            }
        }

        const int dbase = ch * DCHUNK;
        const float* xrow = xs + tid * XS_STRIDE;
#pragma unroll
        for (int d = 0; d < DCHUNK; d += 4) {
            ulonglong2 xv = *reinterpret_cast<const ulonglong2*>(xrow + d);
            const float* wb = w1p + (dbase + d) * QDIM;  // block base (d even)
#pragma unroll
            for (int m = 0; m < 8; m++) {
                ulonglong2 w = *reinterpret_cast<const ulonglong2*>(wb + 4 * m);
                ffma2(acc[2 * m],     xv.x, w.x);
                ffma2(acc[2 * m + 1], xv.x, w.y);
            }
#pragma unroll
            for (int m = 0; m < 8; m++) {
                ulonglong2 w = *reinterpret_cast<const ulonglong2*>(wb + 32 + 4 * m);
                ffma2(acc[2 * m],     xv.y, w.x);
                ffma2(acc[2 * m + 1], xv.y, w.y);
            }
        }
        __syncthreads();
    }

    // ---- epilogue: z = cos(relu(h+b1)+theta), store duplicated ----
#pragma unroll
    for (int q = 0; q < QDIM; q++) {
        float2 a = unpk(acc[q]);
        float h = a.x + a.y + b1s[q];
        h = fmaxf(h, 0.0f) + ths[q];
        float z = cosf(h);
        zs[tid * ZS_STRIDE + 2 * q]     = z;
        zs[tid * ZS_STRIDE + 2 * q + 1] = z;
    }
    __syncthreads();

    // ---- GEMM2: W2 in registers, z broadcast, coalesced stores ----
    const int dcol = 4 * tid;
    ulonglong2 w2r[QDIM];
#pragma unroll
    for (int q = 0; q < QDIM; q++) {
        w2r[q] = *reinterpret_cast<const ulonglong2*>(W2 + q * DDIM + dcol);
    }
    float4 b2v = *reinterpret_cast<const float4*>(b2 + dcol);
    const u64 b2p0 = pk(b2v.x, b2v.y);
    const u64 b2p1 = pk(b2v.z, b2v.w);

    for (int r = 0; r < ROWS; r++) {
        u64 a0 = b2p0;
        u64 a1 = b2p1;
        const float* zr = zs + r * ZS_STRIDE;
#pragma unroll
        for (int m = 0; m < 8; m++) {
            ulonglong2 zd = *reinterpret_cast<const ulonglong2*>(zr + 4 * m);
            ffma2(a0, zd.x, w2r[2 * m].x);
            ffma2(a1, zd.x, w2r[2 * m].y);
            ffma2(a0, zd.y, w2r[2 * m + 1].x);
            ffma2(a1, zd.y, w2r[2 * m + 1].y);
        }
        int gr = row0 + r;
        if (gr < nRows) {
            float2 lo = unpk(a0), hi = unpk(a1);
            float4 o = make_float4(lo.x, lo.y, hi.x, hi.y);
            *reinterpret_cast<float4*>(out + (size_t)gr * DDIM + dcol) = o;
        }
    }
}

extern "C" void kernel_launch(void* const* d_in, const int* in_sizes, int n_in,
                              void* d_out, int out_size) {
    const float* x     = (const float*)d_in[0];
    const float* W1    = (const float*)d_in[1];
    const float* b1    = (const float*)d_in[2];
    const float* theta = (const float*)d_in[3];
    const float* W2    = (const float*)d_in[4];
    const float* b2    = (const float*)d_in[5];
    float* out = (float*)d_out;

    int nRows = in_sizes[0] / DDIM;                 // 32768
    int grid  = (nRows + ROWS - 1) / ROWS;          // 128

    size_t smem = (size_t)(DDIM * QDIM + ROWS * XS_STRIDE + ROWS * ZS_STRIDE + 2 * QDIM)
                  * sizeof(float);                  // ~139 KB
    cudaFuncSetAttribute(ffq_kernel, cudaFuncAttributeMaxDynamicSharedMemorySize,
                         (int)smem);

    ffq_kernel<<<grid, NTHREADS, smem>>>(x, W1, b1, theta, W2, b2, out, nRows);
}